// round 5
// baseline (speedup 1.0000x reference)
#include <cuda_runtime.h>
#include <cstdint>

// GraphAttention collapsed form (validated R1-R4, rel_err ~2e-7):
//   v[b,n] = x[b, NEF + n];  c1 = W.a[:64], c2 = W.a[64:]
//   e(i,o) = c1*v[i] + c2*v[(i+o)%N], o in [0,17)
//   w = exp(lrelu(e)) = (e>0) ? exp(c1 vi)*exp(c2 vj) : exp(.01 c1 vi)*exp(.01 c2 vj)
//   denom[b] = sum w;  s[i] = sum_o w*vj;  out[b,i,f] = lrelu(W[f]*s[i]/denom)
//
// R5: 8-CTA cluster per batch. Factorized exp (4 MUFU/node, not 17).
// Push-model denom exchange: smem mbarrier (8 arrivals) + st.shared::cluster,
// with the mandatory init-visibility cluster barrier ARRIVEd before compute
// and WAITed after it (latency hidden). No trailing cluster sync needed
// (push-only traffic; local mbarrier wait proves all inbound writes landed).

#define NB      8
#define NN      4096
#define NOFF    17
#define FOUT    64
#define NEF     4096
#define CPB     8
#define TPB     512
#define BNODES  512
#define GRID    (NB * CPB)

__device__ __forceinline__ float lrelu(float z) { return fmaxf(z, 0.01f * z); }

__device__ __forceinline__ float warp_sum(float p) {
#pragma unroll
    for (int off = 16; off > 0; off >>= 1)
        p += __shfl_down_sync(0xffffffffu, p, off);
    return p;
}

__device__ __forceinline__ uint32_t smem_u32(const void* p) {
    uint32_t r;
    asm("{ .reg .u64 t; cvta.to.shared.u64 t, %1; cvt.u32.u64 %0, t; }"
        : "=r"(r) : "l"(p));
    return r;
}

__global__ void __launch_bounds__(TPB, 1) __cluster_dims__(CPB, 1, 1)
ga_fused(const float* __restrict__ x,
         const float* __restrict__ W,
         const float* __restrict__ a,
         float* __restrict__ out) {
    __shared__ float4 sv4[BNODES + 16];   // {v, E2, F2, -} per node
    __shared__ float  ssn[BNODES];
    __shared__ float  sW[FOUT];
    __shared__ float  sred[16];
    __shared__ float  sc[2];
    __shared__ float  slots[CPB];         // partial denom from each cluster rank
    __shared__ float  ssinv;
    __shared__ __align__(8) uint64_t mbar;

    const int b    = blockIdx.x >> 3;
    const int rank = blockIdx.x & (CPB - 1);
    const int base = rank * BNODES;
    const float* v = x + (size_t)b * (NEF + NN) + NEF;
    const int t    = threadIdx.x;
    const int warp = t >> 5;
    const int lane = t & 31;

    const uint32_t mbar_a = smem_u32(&mbar);

    if (t == 0)
        asm volatile("mbarrier.init.shared.b64 [%0], %1;"
                     :: "r"(mbar_a), "r"((uint32_t)CPB) : "memory");

    // Own-node value (+16-node tail on warp 0).
    const float vreg  = v[(base + t) & (NN - 1)];
    const float vtail = (t < 16) ? v[(base + BNODES + t) & (NN - 1)] : 0.0f;
    sv4[t].x = vreg;
    if (t < 16) sv4[BNODES + t].x = vtail;

    if (warp == 14) {            // c1 = W . a[:64]
        float p = fmaf(W[lane], a[lane], W[lane + 32] * a[lane + 32]);
        p = warp_sum(p);
        if (lane == 0) sc[0] = p;
    } else if (warp == 15) {     // c2 = W . a[64:]
        float p = fmaf(W[lane], a[64 + lane], W[lane + 32] * a[96 + lane]);
        p = warp_sum(p);
        if (lane == 0) sc[1] = p;
    } else if (warp == 13) {
        sW[lane]      = W[lane];
        sW[lane + 32] = W[lane + 32];
    }
    __syncthreads();                                   // c1,c2,sW,mbar-init visible

    // Publish mbar init to the cluster (release); wait comes after compute.
    asm volatile("barrier.cluster.arrive.aligned;" ::: "memory");

    const float c1 = sc[0], c2 = sc[1];
    const float E1 = __expf(c1 * vreg);
    const float F1 = __expf(0.01f * c1 * vreg);
    sv4[t].y = __expf(c2 * vreg);
    sv4[t].z = __expf(0.01f * c2 * vreg);
    if (t < 16) {
        sv4[BNODES + t].y = __expf(c2 * vtail);
        sv4[BNODES + t].z = __expf(0.01f * c2 * vtail);
    }
    const float4 wvec = ((const float4*)sW)[t & 15];   // store-phase weights
    __syncthreads();

    // Edge loop: 17 edges, 1 LDS.128 each, no MUFU.
    const float c1vi = c1 * vreg;
    float esum = 0.0f, s = 0.0f;
#pragma unroll
    for (int o = 0; o < NOFF; o++) {
        const float4 q = sv4[t + o];
        const float  e = fmaf(c2, q.x, c1vi);
        const float  w = (e > 0.0f) ? (E1 * q.y) : (F1 * q.z);
        esum += w;
        s = fmaf(w, q.x, s);
    }
    ssn[t] = s;

    const float ws = warp_sum(esum);
    if (lane == 0) sred[warp] = ws;
    __syncthreads();

    // By now ~800+ cycles since arrive: the cluster barrier is nearly free.
    asm volatile("barrier.cluster.wait.aligned;" ::: "memory");

    if (t == 0) {
        float part = 0.0f;
#pragma unroll
        for (int k = 0; k < 16; k++) part += sred[k];

        // Push partial into every peer's slots[rank] + arrive on their mbar.
        const uint32_t slot_a = smem_u32(&slots[rank]);
#pragma unroll
        for (int r = 0; r < CPB; r++) {
            uint32_t rs, rm;
            asm("mapa.shared::cluster.u32 %0, %1, %2;"
                : "=r"(rs) : "r"(slot_a), "r"((uint32_t)r));
            asm volatile("st.shared::cluster.f32 [%0], %1;"
                         :: "r"(rs), "f"(part) : "memory");
            asm("mapa.shared::cluster.u32 %0, %1, %2;"
                : "=r"(rm) : "r"(mbar_a), "r"((uint32_t)r));
            asm volatile("mbarrier.arrive.release.cluster.shared::cluster.b64 _, [%0];"
                         :: "r"(rm) : "memory");
        }

        // Wait for all 8 inbound partials (acquire at cluster scope).
        uint32_t done;
        asm volatile(
            "{\n\t.reg .pred p;\n\t"
            "mbarrier.try_wait.parity.acquire.cluster.shared::cta.b64 p, [%1], %2;\n\t"
            "selp.b32 %0, 1, 0, p;\n\t}"
            : "=r"(done) : "r"(mbar_a), "r"(0u) : "memory");
        if (!done) {
            asm volatile(
                "{\n\t.reg .pred P1;\n\t"
                "WAIT_LOOP:\n\t"
                "mbarrier.try_wait.parity.acquire.cluster.shared::cta.b64 P1, [%0], %1, 0x989680;\n\t"
                "@P1 bra.uni WAIT_DONE;\n\t"
                "bra.uni WAIT_LOOP;\n\t"
                "WAIT_DONE:\n\t}"
                :: "r"(mbar_a), "r"(0u) : "memory");
        }

        float d = 0.0f;                      // fixed order -> deterministic
#pragma unroll
        for (int k = 0; k < CPB; k++) d += slots[k];
        ssinv = 1.0f / d;
    }
    __syncthreads();

    // Store phase: 512 nodes x 64 feats = 8192 float4, fully coalesced.
    const float inv = ssinv;
    float4* o4 = (float4*)(out + ((size_t)b * NN + base) * FOUT);
    const int nbase = t >> 4;
#pragma unroll
    for (int k = 0; k < 16; k++) {
        const int   node = nbase + k * 32;
        const float sn   = ssn[node] * inv;
        float4 r;
        r.x = lrelu(sn * wvec.x);
        r.y = lrelu(sn * wvec.y);
        r.z = lrelu(sn * wvec.z);
        r.w = lrelu(sn * wvec.w);
        o4[t + k * TPB] = r;
    }
}

extern "C" void kernel_launch(void* const* d_in, const int* in_sizes, int n_in,
                              void* d_out, int out_size) {
    const float* x = (const float*)d_in[0];
    const float* W = (const float*)d_in[1];
    const float* a = (const float*)d_in[2];
    float* out = (float*)d_out;

    ga_fused<<<GRID, TPB>>>(x, W, a, out);
}

// round 6
// speedup vs baseline: 1.6882x; 1.6882x over previous
#include <cuda_runtime.h>
#include <cstdint>

// GraphAttention collapsed form (validated R1-R5, rel_err ~2e-7):
//   v[b,n] = x[b, NEF + n];  c1 = W.a[:64], c2 = W.a[64:]
//   w(i,o) = exp(lrelu(c1*v[i] + c2*v[(i+o)%N])), o in [0,17)
//   denom[b] = sum w;  s[i] = sum_o w*v[(i+o)%N]
//   out[b,i,f] = lrelu(W[f]*s[i]) / denom[b]
//
// R6 = R4 skeleton + push-model denom exchange:
//   warp0 lanes 0-7 push this CTA's partial into all 8 peers' slots[rank]
//   (parallel st.shared::cluster, fire-and-forget) BEFORE one cluster
//   barrier (arrive=release, wait=acquire). Post-barrier each CTA sums its
//   LOCAL slots -- no DSMEM pull, no mbarrier, no trailing cluster sync,
//   no cross-replay state.

#define NB      8
#define NN      4096
#define NOFF    17
#define FOUT    64
#define NEF     4096
#define CPB     8
#define TPB     512
#define BNODES  512
#define GRID    (NB * CPB)

__device__ __forceinline__ float lrelu(float z) { return fmaxf(z, 0.01f * z); }

__device__ __forceinline__ float warp_sum(float p) {
#pragma unroll
    for (int off = 16; off > 0; off >>= 1)
        p += __shfl_down_sync(0xffffffffu, p, off);
    return p;
}

__device__ __forceinline__ uint32_t smem_u32(const void* p) {
    uint32_t r;
    asm("{ .reg .u64 t; cvta.to.shared.u64 t, %1; cvt.u32.u64 %0, t; }"
        : "=r"(r) : "l"(p));
    return r;
}

__global__ void __launch_bounds__(TPB, 1) __cluster_dims__(CPB, 1, 1)
ga_fused(const float* __restrict__ x,
         const float* __restrict__ W,
         const float* __restrict__ a,
         float* __restrict__ out) {
    __shared__ float sv[BNODES + 16];
    __shared__ float ssn[BNODES];
    __shared__ float sW[FOUT];
    __shared__ float sred[16];
    __shared__ float sc[2];
    __shared__ float slots[CPB];   // inbound partial from each cluster rank
    __shared__ float ssinv;

    const int b    = blockIdx.x >> 3;
    const int rank = blockIdx.x & (CPB - 1);
    const int base = rank * BNODES;
    const float* v = x + (size_t)b * (NEF + NN) + NEF;
    const int t    = threadIdx.x;
    const int warp = t >> 5;
    const int lane = t & 31;

    // Parallel prologue (disjoint warp roles):
    sv[t] = v[(base + t) & (NN - 1)];
    if (t < 16) sv[BNODES + t] = v[(base + BNODES + t) & (NN - 1)];
    if (warp == 14) {            // c1 = W . a[:64]
        float p = fmaf(W[lane], a[lane], W[lane + 32] * a[lane + 32]);
        p = warp_sum(p);
        if (lane == 0) sc[0] = p;
    } else if (warp == 15) {     // c2 = W . a[64:]
        float p = fmaf(W[lane], a[64 + lane], W[lane + 32] * a[96 + lane]);
        p = warp_sum(p);
        if (lane == 0) sc[1] = p;
    } else if (warp == 13) {
        sW[lane]      = W[lane];
        sW[lane + 32] = W[lane + 32];
    }
    __syncthreads();

    // Store-phase weights hoisted now (constant per thread).
    const float4 wvec = ((const float4*)sW)[t & 15];

    // Phase 1: per-node numerator + thread-local exp-sum (1 node/thread).
    const float c1 = sc[0], c2 = sc[1];
    const float vi = sv[t];
    float esum = 0.0f, s = 0.0f;
#pragma unroll
    for (int o = 0; o < NOFF; o++) {
        const float vj = sv[t + o];
        const float w  = __expf(lrelu(fmaf(c1, vi, c2 * vj)));
        esum += w;
        s = fmaf(w, vj, s);
    }
    ssn[t] = s;

    const float ws = warp_sum(esum);
    if (lane == 0) sred[warp] = ws;
    __syncthreads();

    // Warp 0: combine 16 warp-partials (butterfly -> all lanes hold total),
    // then lanes 0-7 push the CTA partial into every peer's slots[rank].
    if (warp == 0) {
        float p = (lane < 16) ? sred[lane] : 0.0f;
#pragma unroll
        for (int off = 8; off > 0; off >>= 1)
            p += __shfl_xor_sync(0xffffffffu, p, off);
        if (lane < CPB) {
            const uint32_t laddr = smem_u32(&slots[rank]);
            uint32_t raddr;
            asm("mapa.shared::cluster.u32 %0, %1, %2;"
                : "=r"(raddr) : "r"(laddr), "r"((uint32_t)lane));
            asm volatile("st.shared::cluster.f32 [%0], %1;"
                         :: "r"(raddr), "f"(p) : "memory");
        }
    }
    __syncthreads();   // all warps past push-issue before arrive

    // One cluster barrier: arrive releases our pushes, wait acquires peers'.
    asm volatile("barrier.cluster.arrive.aligned;" ::: "memory");
    asm volatile("barrier.cluster.wait.aligned;"   ::: "memory");

    // Local combine of the 8 inbound partials (fixed shape -> deterministic).
    if (warp == 0) {
        float p = (lane < CPB) ? slots[lane] : 0.0f;
#pragma unroll
        for (int off = 4; off > 0; off >>= 1)
            p += __shfl_xor_sync(0xffffffffu, p, off);
        if (lane == 0) ssinv = 1.0f / p;
    }
    __syncthreads();

    // Phase 2: 512 nodes x 64 feats = 8192 float4, fully coalesced.
    const float inv = ssinv;
    float4* o4 = (float4*)(out + ((size_t)b * NN + base) * FOUT);
    const int nbase = t >> 4;
#pragma unroll
    for (int k = 0; k < 16; k++) {
        const float sn = ssn[nbase + k * 32] * inv;
        float4 r;
        r.x = lrelu(sn * wvec.x);
        r.y = lrelu(sn * wvec.y);
        r.z = lrelu(sn * wvec.z);
        r.w = lrelu(sn * wvec.w);
        o4[t + k * TPB] = r;
    }
}

extern "C" void kernel_launch(void* const* d_in, const int* in_sizes, int n_in,
                              void* d_out, int out_size) {
    const float* x = (const float*)d_in[0];
    const float* W = (const float*)d_in[1];
    const float* a = (const float*)d_in[2];
    float* out = (float*)d_out;

    ga_fused<<<GRID, TPB>>>(x, W, a, out);
}